// round 1
// baseline (speedup 1.0000x reference)
#include <cuda_runtime.h>
#include <math.h>

#define BSZ    2
#define SEQ    2048
#define DMODEL 2048
#define NHEADS 16
#define HDIM   128
#define BH     (BSZ*NHEADS)
#define MROWS  (BSZ*SEQ)

// ---- scratch (device globals: no allocation allowed) ----
__device__ float g_q[BH*SEQ*HDIM];      // 33.5 MB, [b,h,s,hd]
__device__ float g_k[BH*SEQ*HDIM];
__device__ float g_v[BH*SEQ*HDIM];
__device__ float g_attn[MROWS*DMODEL];  // [b,s,h*HD+hd]
__device__ float g_cos[SEQ*64];
__device__ float g_sin[SEQ*64];

// =================== RoPE cache (fp64 for accuracy) ===================
__global__ void rope_cache_kernel() {
    int idx = blockIdx.x * blockDim.x + threadIdx.x;
    if (idx >= SEQ * 64) return;
    int pos = idx >> 6;
    int j   = idx & 63;
    double e    = (double)(2 * j) / 128.0;
    double invf = pow(10000.0, -e);
    double ang  = (double)pos * invf;
    g_cos[idx] = (float)cos(ang);
    g_sin[idx] = (float)sin(ang);
}

// =================== RoPE apply (in-place on q,k) ===================
__global__ void rope_apply_kernel() {
    int idx = blockIdx.x * blockDim.x + threadIdx.x;
    if (idx >= BH * SEQ * 64) return;
    int j   = idx & 63;
    int row = idx >> 6;            // global (b,h,s) row
    int s   = row & (SEQ - 1);
    float c  = g_cos[s * 64 + j];
    float sn = g_sin[s * 64 + j];
    float* qp = g_q + (size_t)row * HDIM;
    float* kp = g_k + (size_t)row * HDIM;
    float q1 = qp[j], q2 = qp[j + 64];
    qp[j]      = q1 * c - q2 * sn;
    qp[j + 64] = q2 * c + q1 * sn;
    float k1 = kp[j], k2 = kp[j + 64];
    kp[j]      = k1 * c - k2 * sn;
    kp[j + 64] = k2 * c + k1 * sn;
}

// =================== SGEMM: C[m,n] = sum_k A[m,k]*B[n,k] ===================
// A [M,K] row-major, B [N,K] row-major. 128x128 tile, BK=8, 256 thr, 8x8/thread.
// mode 0: C[m*N+n] (row-major)       mode 1: scatter to [b,h,s,hd] heads layout
__global__ __launch_bounds__(256)
void sgemm_nt(const float* __restrict__ A, const float* __restrict__ B,
              float* __restrict__ C, int M, int N, int K, int mode)
{
    __shared__ float As[8][128];
    __shared__ float Bs[8][128];
    const int tid = threadIdx.x;
    const int tx = tid & 15;
    const int ty = tid >> 4;
    const int bm = blockIdx.y * 128;
    const int bn = blockIdx.x * 128;
    const int lrow = tid >> 1;
    const int lseg = (tid & 1) << 2;

    const float* Ap = A + (size_t)(bm + lrow) * K + lseg;
    const float* Bp = B + (size_t)(bn + lrow) * K + lseg;

    float acc[8][8];
#pragma unroll
    for (int i = 0; i < 8; i++)
#pragma unroll
        for (int j = 0; j < 8; j++) acc[i][j] = 0.f;

    for (int k0 = 0; k0 < K; k0 += 8) {
        float4 av = *(const float4*)(Ap + k0);
        float4 bv = *(const float4*)(Bp + k0);
        As[lseg + 0][lrow] = av.x; As[lseg + 1][lrow] = av.y;
        As[lseg + 2][lrow] = av.z; As[lseg + 3][lrow] = av.w;
        Bs[lseg + 0][lrow] = bv.x; Bs[lseg + 1][lrow] = bv.y;
        Bs[lseg + 2][lrow] = bv.z; Bs[lseg + 3][lrow] = bv.w;
        __syncthreads();
#pragma unroll
        for (int kk = 0; kk < 8; kk++) {
            float a[8], b[8];
            *(float4*)&a[0] = *(const float4*)&As[kk][ty * 8];
            *(float4*)&a[4] = *(const float4*)&As[kk][ty * 8 + 4];
            *(float4*)&b[0] = *(const float4*)&Bs[kk][tx * 8];
            *(float4*)&b[4] = *(const float4*)&Bs[kk][tx * 8 + 4];
#pragma unroll
            for (int i = 0; i < 8; i++)
#pragma unroll
                for (int j = 0; j < 8; j++)
                    acc[i][j] += a[i] * b[j];
        }
        __syncthreads();
    }

    if (mode == 0) {
#pragma unroll
        for (int i = 0; i < 8; i++) {
            int m = bm + ty * 8 + i;
            float* cp = C + (size_t)m * N + bn + tx * 8;
            *(float4*)(cp)     = make_float4(acc[i][0], acc[i][1], acc[i][2], acc[i][3]);
            *(float4*)(cp + 4) = make_float4(acc[i][4], acc[i][5], acc[i][6], acc[i][7]);
        }
    } else {
        // m = b*SEQ + s ; n = h*128 + hd  ->  out[((b*NH+h)*SEQ+s)*HD + hd]
        const int h   = bn >> 7;
        const int hd0 = tx * 8;
#pragma unroll
        for (int i = 0; i < 8; i++) {
            int m = bm + ty * 8 + i;
            int b = m >> 11;
            int s = m & (SEQ - 1);
            float* cp = C + (((size_t)(b * NHEADS + h)) * SEQ + s) * HDIM + hd0;
            *(float4*)(cp)     = make_float4(acc[i][0], acc[i][1], acc[i][2], acc[i][3]);
            *(float4*)(cp + 4) = make_float4(acc[i][4], acc[i][5], acc[i][6], acc[i][7]);
        }
    }
}

// =================== Flash attention (causal) ===================
// grid: (SEQ/64, BH), 256 threads. Online softmax, fp32 everywhere.
#define FP 65            // smem pitch for transposed/P tiles (conflict pad)
#define FLASH_SMEM_FLOATS (128*FP + 128*FP + 64*128 + 64*FP + 3*64)
#define FLASH_SMEM_BYTES  (FLASH_SMEM_FLOATS * 4)

__global__ __launch_bounds__(256)
void flash_fwd(const float* __restrict__ Qg, const float* __restrict__ Kg,
               const float* __restrict__ Vg, float* __restrict__ Og)
{
    extern __shared__ float sm[];
    float* Qt = sm;                  // [128][FP]: Qt[k*FP + m]
    float* Kt = Qt + 128 * FP;       // [128][FP]: Kt[k*FP + n]
    float* Vs = Kt + 128 * FP;       // [64][128]: Vs[kv*128 + hd]
    float* Ps = Vs + 64 * 128;       // [64][FP]:  S/P tile
    float* rm = Ps + 64 * FP;
    float* rl = rm + 64;
    float* ra = rl + 64;

    const int tid = threadIdx.x;
    const int bx  = blockIdx.x;      // query tile
    const int bh  = blockIdx.y;      // (b,h)
    const int m0  = bx * 64;
    const size_t base = (size_t)bh * SEQ * HDIM;

    // load Q tile transposed: Qt[k][m]
    {
        const float* qp = Qg + base + (size_t)m0 * HDIM;
#pragma unroll
        for (int i = 0; i < 8; i++) {
            int lin = i * 256 + tid;       // float4 index within 64x128 tile
            int row = lin >> 5;            // 0..63
            int c4  = lin & 31;            // 0..31
            float4 v = *(const float4*)(qp + row * HDIM + c4 * 4);
            Qt[(c4 * 4 + 0) * FP + row] = v.x;
            Qt[(c4 * 4 + 1) * FP + row] = v.y;
            Qt[(c4 * 4 + 2) * FP + row] = v.z;
            Qt[(c4 * 4 + 3) * FP + row] = v.w;
        }
    }
    if (tid < 64) { rm[tid] = -1e30f; rl[tid] = 0.f; }

    const int tm = tid >> 4, tn = tid & 15;       // S-compute mapping (4x4)
    const int w = tid >> 5, lane = tid & 31;      // PV mapping (8 rows x 4 cols)
    const int r0 = w * 8, c0 = lane * 4;

    float o[8][4];
#pragma unroll
    for (int i = 0; i < 8; i++)
#pragma unroll
        for (int j = 0; j < 4; j++) o[i][j] = 0.f;

    const float scale = 0.08838834764831845f;     // 1/sqrt(128)
    const int ntiles = bx + 1;

    for (int t = 0; t < ntiles; t++) {
        const int n0 = t * 64;
        __syncthreads();   // previous PV finished; Q load / stats visible (1st iter)

        // load K transposed + V natural
        const float* kp = Kg + base + (size_t)n0 * HDIM;
        const float* vp = Vg + base + (size_t)n0 * HDIM;
#pragma unroll
        for (int i = 0; i < 8; i++) {
            int lin = i * 256 + tid;
            int row = lin >> 5;
            int c4  = lin & 31;
            float4 kv = *(const float4*)(kp + row * HDIM + c4 * 4);
            Kt[(c4 * 4 + 0) * FP + row] = kv.x;
            Kt[(c4 * 4 + 1) * FP + row] = kv.y;
            Kt[(c4 * 4 + 2) * FP + row] = kv.z;
            Kt[(c4 * 4 + 3) * FP + row] = kv.w;
            *(float4*)(Vs + row * 128 + c4 * 4) = *(const float4*)(vp + row * HDIM + c4 * 4);
        }
        __syncthreads();

        // S = Q K^T (4x4 per thread)
        float s[4][4];
#pragma unroll
        for (int i = 0; i < 4; i++)
#pragma unroll
            for (int j = 0; j < 4; j++) s[i][j] = 0.f;

        for (int k = 0; k < 128; k++) {
            float a0 = Qt[k * FP + 4 * tm + 0];
            float a1 = Qt[k * FP + 4 * tm + 1];
            float a2 = Qt[k * FP + 4 * tm + 2];
            float a3 = Qt[k * FP + 4 * tm + 3];
            float b0 = Kt[k * FP + 4 * tn + 0];
            float b1 = Kt[k * FP + 4 * tn + 1];
            float b2 = Kt[k * FP + 4 * tn + 2];
            float b3 = Kt[k * FP + 4 * tn + 3];
            s[0][0] += a0 * b0; s[0][1] += a0 * b1; s[0][2] += a0 * b2; s[0][3] += a0 * b3;
            s[1][0] += a1 * b0; s[1][1] += a1 * b1; s[1][2] += a1 * b2; s[1][3] += a1 * b3;
            s[2][0] += a2 * b0; s[2][1] += a2 * b1; s[2][2] += a2 * b2; s[2][3] += a2 * b3;
            s[3][0] += a3 * b0; s[3][1] += a3 * b1; s[3][2] += a3 * b2; s[3][3] += a3 * b3;
        }
        const bool diag = (t == bx);
#pragma unroll
        for (int i = 0; i < 4; i++) {
#pragma unroll
            for (int j = 0; j < 4; j++) {
                float val = s[i][j] * scale;
                if (diag) {
                    int row = m0 + 4 * tm + i;
                    int col = n0 + 4 * tn + j;
                    if (col > row) val = -1e30f;
                }
                Ps[(4 * tm + i) * FP + (4 * tn + j)] = val;
            }
        }
        __syncthreads();

        // online softmax per row (threads 0..63)
        if (tid < 64) {
            int r = tid;
            float mo = rm[r];
            float mx = mo;
            for (int k = 0; k < 64; k++) mx = fmaxf(mx, Ps[r * FP + k]);
            float l = 0.f;
            for (int k = 0; k < 64; k++) {
                float p = __expf(Ps[r * FP + k] - mx);
                Ps[r * FP + k] = p;
                l += p;
            }
            float alpha = __expf(mo - mx);
            rl[r] = rl[r] * alpha + l;
            rm[r] = mx;
            ra[r] = alpha;
        }
        __syncthreads();

        // rescale O and accumulate P*V
        float al[8];
#pragma unroll
        for (int i = 0; i < 8; i++) al[i] = ra[r0 + i];
#pragma unroll
        for (int i = 0; i < 8; i++)
#pragma unroll
            for (int j = 0; j < 4; j++) o[i][j] *= al[i];

        for (int k = 0; k < 64; k++) {
            float4 vv = *(const float4*)(Vs + k * 128 + c0);
#pragma unroll
            for (int i = 0; i < 8; i++) {
                float p = Ps[(r0 + i) * FP + k];   // warp-uniform broadcast
                o[i][0] += p * vv.x;
                o[i][1] += p * vv.y;
                o[i][2] += p * vv.z;
                o[i][3] += p * vv.w;
            }
        }
    }

    // epilogue: divide by l, scatter to [b, s, h*HD+hd]
    const int b = bh >> 4;
    const int h = bh & 15;
#pragma unroll
    for (int i = 0; i < 8; i++) {
        int srow = m0 + r0 + i;
        float inv = 1.f / rl[r0 + i];
        float4 r = make_float4(o[i][0] * inv, o[i][1] * inv, o[i][2] * inv, o[i][3] * inv);
        *(float4*)(Og + ((size_t)(b * SEQ + srow)) * DMODEL + h * HDIM + c0) = r;
    }
}

// =================== launch ===================
extern "C" void kernel_launch(void* const* d_in, const int* in_sizes, int n_in,
                              void* d_out, int out_size)
{
    (void)in_sizes; (void)n_in; (void)out_size;
    const float* hidden = (const float*)d_in[0];
    // d_in[1] = attention_mask (pure causal -1e9: applied analytically)
    // d_in[2] = position_ids   (arange: applied analytically)
    const float* Wq = (const float*)d_in[3];
    const float* Wk = (const float*)d_in[4];
    const float* Wv = (const float*)d_in[5];
    const float* Wo = (const float*)d_in[6];
    float* out = (float*)d_out;

    float *q, *k, *v, *attn;
    cudaGetSymbolAddress((void**)&q,    g_q);
    cudaGetSymbolAddress((void**)&k,    g_k);
    cudaGetSymbolAddress((void**)&v,    g_v);
    cudaGetSymbolAddress((void**)&attn, g_attn);

    cudaFuncSetAttribute(flash_fwd, cudaFuncAttributeMaxDynamicSharedMemorySize,
                         FLASH_SMEM_BYTES);

    rope_cache_kernel<<<(SEQ * 64 + 255) / 256, 256>>>();

    dim3 ggrid(DMODEL / 128, MROWS / 128);   // (16, 32)
    sgemm_nt<<<ggrid, 256>>>(hidden, Wq, q, MROWS, DMODEL, DMODEL, 1);
    sgemm_nt<<<ggrid, 256>>>(hidden, Wk, k, MROWS, DMODEL, DMODEL, 1);
    sgemm_nt<<<ggrid, 256>>>(hidden, Wv, v, MROWS, DMODEL, DMODEL, 1);

    rope_apply_kernel<<<(BH * SEQ * 64 + 255) / 256, 256>>>();

    flash_fwd<<<dim3(SEQ / 64, BH), 256, FLASH_SMEM_BYTES>>>(q, k, v, attn);

    sgemm_nt<<<ggrid, 256>>>(attn, Wo, out, MROWS, DMODEL, DMODEL, 0);
}

// round 3
// speedup vs baseline: 1.6571x; 1.6571x over previous
#include <cuda_runtime.h>
#include <math.h>
#include <stdint.h>

#define BSZ    2
#define SEQ    2048
#define DMODEL 2048
#define NHEADS 16
#define HDIM   128
#define BH     (BSZ*NHEADS)
#define MROWS  (BSZ*SEQ)

// ---- scratch (device globals: no allocation allowed) ----
__device__ float g_q[BH*SEQ*HDIM];      // [b,h,s,hd]
__device__ float g_k[BH*SEQ*HDIM];
__device__ float g_v[BH*SEQ*HDIM];
__device__ float g_attn[MROWS*DMODEL];  // [b,s,h*HD+hd]
__device__ float g_cos[SEQ*64];
__device__ float g_sin[SEQ*64];

__device__ __forceinline__ float to_tf32(float x) {
    float y;
    asm("cvt.rna.tf32.f32 %0, %1;" : "=f"(y) : "f"(x));
    return y;
}

// mma.m16n8k8 tf32: D(16x8) += A(16x8) * B(8x8)
__device__ __forceinline__ void mma_tf32(float* c, const uint32_t* a, const uint32_t* b) {
    asm volatile(
        "mma.sync.aligned.m16n8k8.row.col.f32.tf32.tf32.f32 "
        "{%0,%1,%2,%3}, {%4,%5,%6,%7}, {%8,%9}, {%0,%1,%2,%3};"
        : "+f"(c[0]), "+f"(c[1]), "+f"(c[2]), "+f"(c[3])
        : "r"(a[0]), "r"(a[1]), "r"(a[2]), "r"(a[3]), "r"(b[0]), "r"(b[1]));
}

// =================== RoPE cache (fp64 for accuracy) ===================
__global__ void rope_cache_kernel() {
    int idx = blockIdx.x * blockDim.x + threadIdx.x;
    if (idx >= SEQ * 64) return;
    int pos = idx >> 6;
    int j   = idx & 63;
    double e    = (double)(2 * j) / 128.0;
    double invf = pow(10000.0, -e);
    double ang  = (double)pos * invf;
    g_cos[idx] = (float)cos(ang);
    g_sin[idx] = (float)sin(ang);
}

// =================== RoPE apply (in-place on q,k) ===================
__global__ void rope_apply_kernel() {
    int idx = blockIdx.x * blockDim.x + threadIdx.x;
    if (idx >= BH * SEQ * 64) return;
    int j   = idx & 63;
    int row = idx >> 6;
    int s   = row & (SEQ - 1);
    float c  = g_cos[s * 64 + j];
    float sn = g_sin[s * 64 + j];
    float* qp = g_q + (size_t)row * HDIM;
    float* kp = g_k + (size_t)row * HDIM;
    float q1 = qp[j], q2 = qp[j + 64];
    qp[j]      = q1 * c - q2 * sn;
    qp[j + 64] = q2 * c + q1 * sn;
    float k1 = kp[j], k2 = kp[j + 64];
    kp[j]      = k1 * c - k2 * sn;
    kp[j + 64] = k2 * c + k1 * sn;
}

// =================== TF32 tensor-core GEMM ===================
// C[m,n] = sum_k A[m,k]*B[n,k].  A[M,K], B[N,K] row-major, K=2048.
// CTA: 128x128 tile, 256 threads = 8 warps (2m x 4n), warp tile 64x32.
// K stage = 16. smem in fragment-major layout:
//   As[kb(2)][mt(8)][lane(32)][4]  (a0=A[g][tig], a1=A[g+8][tig], a2=A[g][tig+4], a3=A[g+8][tig+4])
//   Bs[kb(2)][nt(16)][lane(32)][2] (b0=B[tig][gcol], b1=B[tig+4][gcol])
// mode 0: row-major C    mode 1: scatter to [b,h,s,hd]
#define GEMM_K  DMODEL
#define KSTAGES (GEMM_K / 16)   // 128

__global__ __launch_bounds__(256, 2)
void tf32_gemm(const float* __restrict__ A, const float* __restrict__ B,
               float* __restrict__ C, int mode)
{
    __shared__ float As[2048];
    __shared__ float Bs[2048];

    const int tid  = threadIdx.x;
    const int wid  = tid >> 5;
    const int lane = tid & 31;
    const int bm = blockIdx.y * 128;
    const int bn = blockIdx.x * 128;
    const int wm = wid >> 2;          // 0..1  (64 rows)
    const int wn = wid & 3;           // 0..3  (32 cols)

    // ---- global load + fragment-scatter mapping (2 float4 per operand) ----
    int srow[2], sc4[2];
    int aBase[2], bBase[2];
    const float4* Ap[2];
    const float4* Bp[2];
#pragma unroll
    for (int i = 0; i < 2; i++) {
        int f   = i * 256 + tid;      // 0..511 float4 slots of the 128x16 tile
        int row = f >> 2;             // 0..127
        int c4  = f & 3;              // float4 along k (k0 = c4*4)
        srow[i] = row; sc4[i] = c4;
        int kb = c4 >> 1, khalf = c4 & 1;
        {   // A: mt/g/hi
            int mt = row >> 4, ml = row & 15, g = ml & 7, hi = ml >> 3;
            aBase[i] = (kb * 8 + mt) * 128 + g * 16 + hi + khalf * 2;
        }
        {   // B: nt/g
            int nt = row >> 3, g = row & 7;
            bBase[i] = (kb * 16 + nt) * 64 + g * 8 + khalf;
        }
        Ap[i] = (const float4*)(A + (size_t)(bm + row) * GEMM_K) + c4;
        Bp[i] = (const float4*)(B + (size_t)(bn + row) * GEMM_K) + c4;
    }

    float acc[4][4][4];
#pragma unroll
    for (int mt = 0; mt < 4; mt++)
#pragma unroll
        for (int nt = 0; nt < 4; nt++)
#pragma unroll
            for (int e = 0; e < 4; e++) acc[mt][nt][e] = 0.f;

    // prefetch stage 0
    float4 pa[2], pb[2];
#pragma unroll
    for (int i = 0; i < 2; i++) { pa[i] = Ap[i][0]; pb[i] = Bp[i][0]; }

    const uint32_t* aFrag = (const uint32_t*)As + ((wm * 4) * 32 + lane) * 4;
    const uint32_t* bFrag = (const uint32_t*)Bs + ((wn * 4) * 32 + lane) * 2;

#pragma unroll 1
    for (int ks = 0; ks < KSTAGES; ks++) {
        __syncthreads();   // previous stage MMAs done
        // scatter current prefetch into fragment-major smem (tf32-rounded)
#pragma unroll
        for (int i = 0; i < 2; i++) {
            float av[4] = {pa[i].x, pa[i].y, pa[i].z, pa[i].w};
            float bv[4] = {pb[i].x, pb[i].y, pb[i].z, pb[i].w};
#pragma unroll
            for (int e = 0; e < 4; e++) {
                As[aBase[i] + e * 4] = to_tf32(av[e]);
                Bs[bBase[i] + e * 2] = to_tf32(bv[e]);
            }
        }
        __syncthreads();

        // issue next-stage global loads (overlap with MMA)
        if (ks + 1 < KSTAGES) {
#pragma unroll
            for (int i = 0; i < 2; i++) {
                pa[i] = Ap[i][(ks + 1) * 4];
                pb[i] = Bp[i][(ks + 1) * 4];
            }
        }

        // MMAs over the 2 k8-blocks of this stage
#pragma unroll
        for (int kb = 0; kb < 2; kb++) {
            uint32_t a[4][4], b[4][2];
#pragma unroll
            for (int mt = 0; mt < 4; mt++)
                *(uint4*)a[mt] = *(const uint4*)(aFrag + (kb * 8 + mt) * 128);
#pragma unroll
            for (int nt = 0; nt < 4; nt++)
                *(uint2*)b[nt] = *(const uint2*)(bFrag + (kb * 16 + nt) * 64);
#pragma unroll
            for (int mt = 0; mt < 4; mt++)
#pragma unroll
                for (int nt = 0; nt < 4; nt++)
                    mma_tf32(acc[mt][nt], a[mt], b[nt]);
        }
    }

    // ---- epilogue ----
    const int g = lane >> 2, tig = lane & 3;
#pragma unroll
    for (int mt = 0; mt < 4; mt++) {
#pragma unroll
        for (int nt = 0; nt < 4; nt++) {
            int row = bm + wm * 64 + mt * 16 + g;
            int col = bn + wn * 32 + nt * 8 + tig * 2;
            float* c0;
            size_t rstride;
            if (mode == 0) {
                c0 = C + (size_t)row * DMODEL + col;
                rstride = DMODEL;
            } else {
                int b = row >> 11, s = row & (SEQ - 1);
                int h = col >> 7, hd = col & 127;
                c0 = C + (((size_t)(b * NHEADS + h)) * SEQ + s) * HDIM + hd;
                rstride = HDIM;   // rows +8 stay in same (b,h) since bm%128==0, 16-row tiles
            }
            *(float2*)c0 = make_float2(acc[mt][nt][0], acc[mt][nt][1]);
            *(float2*)(c0 + 8 * rstride) = make_float2(acc[mt][nt][2], acc[mt][nt][3]);
        }
    }
}

// =================== Flash attention (causal) ===================
#define FP 65
#define FLASH_SMEM_FLOATS (128*FP + 128*FP + 64*128 + 64*FP + 3*64)
#define FLASH_SMEM_BYTES  (FLASH_SMEM_FLOATS * 4)

__global__ __launch_bounds__(256)
void flash_fwd(const float* __restrict__ Qg, const float* __restrict__ Kg,
               const float* __restrict__ Vg, float* __restrict__ Og)
{
    extern __shared__ float smf[];
    float* Qt = smf;
    float* Kt = Qt + 128 * FP;
    float* Vs = Kt + 128 * FP;
    float* Ps = Vs + 64 * 128;
    float* rm = Ps + 64 * FP;
    float* rl = rm + 64;
    float* ra = rl + 64;

    const int tid = threadIdx.x;
    const int bx  = blockIdx.x;
    const int bh  = blockIdx.y;
    const int m0  = bx * 64;
    const size_t base = (size_t)bh * SEQ * HDIM;

    {
        const float* qp = Qg + base + (size_t)m0 * HDIM;
#pragma unroll
        for (int i = 0; i < 8; i++) {
            int lin = i * 256 + tid;
            int row = lin >> 5;
            int c4  = lin & 31;
            float4 v = *(const float4*)(qp + row * HDIM + c4 * 4);
            Qt[(c4 * 4 + 0) * FP + row] = v.x;
            Qt[(c4 * 4 + 1) * FP + row] = v.y;
            Qt[(c4 * 4 + 2) * FP + row] = v.z;
            Qt[(c4 * 4 + 3) * FP + row] = v.w;
        }
    }
    if (tid < 64) { rm[tid] = -1e30f; rl[tid] = 0.f; }

    const int tm = tid >> 4, tn = tid & 15;
    const int w = tid >> 5, lane = tid & 31;
    const int r0 = w * 8, c0 = lane * 4;

    float o[8][4];
#pragma unroll
    for (int i = 0; i < 8; i++)
#pragma unroll
        for (int j = 0; j < 4; j++) o[i][j] = 0.f;

    const float scale = 0.08838834764831845f;
    const int ntiles = bx + 1;

    for (int t = 0; t < ntiles; t++) {
        const int n0 = t * 64;
        __syncthreads();

        const float* kp = Kg + base + (size_t)n0 * HDIM;
        const float* vp = Vg + base + (size_t)n0 * HDIM;
#pragma unroll
        for (int i = 0; i < 8; i++) {
            int lin = i * 256 + tid;
            int row = lin >> 5;
            int c4  = lin & 31;
            float4 kv = *(const float4*)(kp + row * HDIM + c4 * 4);
            Kt[(c4 * 4 + 0) * FP + row] = kv.x;
            Kt[(c4 * 4 + 1) * FP + row] = kv.y;
            Kt[(c4 * 4 + 2) * FP + row] = kv.z;
            Kt[(c4 * 4 + 3) * FP + row] = kv.w;
            *(float4*)(Vs + row * 128 + c4 * 4) = *(const float4*)(vp + row * HDIM + c4 * 4);
        }
        __syncthreads();

        float s[4][4];
#pragma unroll
        for (int i = 0; i < 4; i++)
#pragma unroll
            for (int j = 0; j < 4; j++) s[i][j] = 0.f;

        for (int k = 0; k < 128; k++) {
            float a0 = Qt[k * FP + 4 * tm + 0];
            float a1 = Qt[k * FP + 4 * tm + 1];
            float a2 = Qt[k * FP + 4 * tm + 2];
            float a3 = Qt[k * FP + 4 * tm + 3];
            float b0 = Kt[k * FP + 4 * tn + 0];
            float b1 = Kt[k * FP + 4 * tn + 1];
            float b2 = Kt[k * FP + 4 * tn + 2];
            float b3 = Kt[k * FP + 4 * tn + 3];
            s[0][0] += a0 * b0; s[0][1] += a0 * b1; s[0][2] += a0 * b2; s[0][3] += a0 * b3;
            s[1][0] += a1 * b0; s[1][1] += a1 * b1; s[1][2] += a1 * b2; s[1][3] += a1 * b3;
            s[2][0] += a2 * b0; s[2][1] += a2 * b1; s[2][2] += a2 * b2; s[2][3] += a2 * b3;
            s[3][0] += a3 * b0; s[3][1] += a3 * b1; s[3][2] += a3 * b2; s[3][3] += a3 * b3;
        }
        const bool diag = (t == bx);
#pragma unroll
        for (int i = 0; i < 4; i++) {
#pragma unroll
            for (int j = 0; j < 4; j++) {
                float val = s[i][j] * scale;
                if (diag) {
                    int row = m0 + 4 * tm + i;
                    int col = n0 + 4 * tn + j;
                    if (col > row) val = -1e30f;
                }
                Ps[(4 * tm + i) * FP + (4 * tn + j)] = val;
            }
        }
        __syncthreads();

        if (tid < 64) {
            int r = tid;
            float mo = rm[r];
            float mx = mo;
            for (int k = 0; k < 64; k++) mx = fmaxf(mx, Ps[r * FP + k]);
            float l = 0.f;
            for (int k = 0; k < 64; k++) {
                float p = __expf(Ps[r * FP + k] - mx);
                Ps[r * FP + k] = p;
                l += p;
            }
            float alpha = __expf(mo - mx);
            rl[r] = rl[r] * alpha + l;
            rm[r] = mx;
            ra[r] = alpha;
        }
        __syncthreads();

        float al[8];
#pragma unroll
        for (int i = 0; i < 8; i++) al[i] = ra[r0 + i];
#pragma unroll
        for (int i = 0; i < 8; i++)
#pragma unroll
            for (int j = 0; j < 4; j++) o[i][j] *= al[i];

        for (int k = 0; k < 64; k++) {
            float4 vv = *(const float4*)(Vs + k * 128 + c0);
#pragma unroll
            for (int i = 0; i < 8; i++) {
                float p = Ps[(r0 + i) * FP + k];
                o[i][0] += p * vv.x;
                o[i][1] += p * vv.y;
                o[i][2] += p * vv.z;
                o[i][3] += p * vv.w;
            }
        }
    }

    const int b = bh >> 4;
    const int h = bh & 15;
#pragma unroll
    for (int i = 0; i < 8; i++) {
        int srow = m0 + r0 + i;
        float inv = 1.f / rl[r0 + i];
        float4 r = make_float4(o[i][0] * inv, o[i][1] * inv, o[i][2] * inv, o[i][3] * inv);
        *(float4*)(Og + ((size_t)(b * SEQ + srow)) * DMODEL + h * HDIM + c0) = r;
    }
}

// =================== launch ===================
extern "C" void kernel_launch(void* const* d_in, const int* in_sizes, int n_in,
                              void* d_out, int out_size)
{
    (void)in_sizes; (void)n_in; (void)out_size;
    const float* hidden = (const float*)d_in[0];
    const float* Wq = (const float*)d_in[3];
    const float* Wk = (const float*)d_in[4];
    const float* Wv = (const float*)d_in[5];
    const float* Wo = (const float*)d_in[6];
    float* out = (float*)d_out;

    float *q, *k, *v, *attn;
    cudaGetSymbolAddress((void**)&q,    g_q);
    cudaGetSymbolAddress((void**)&k,    g_k);
    cudaGetSymbolAddress((void**)&v,    g_v);
    cudaGetSymbolAddress((void**)&attn, g_attn);

    cudaFuncSetAttribute(flash_fwd, cudaFuncAttributeMaxDynamicSharedMemorySize,
                         FLASH_SMEM_BYTES);

    rope_cache_kernel<<<(SEQ * 64 + 255) / 256, 256>>>();

    dim3 ggrid(DMODEL / 128, MROWS / 128);   // (16, 32)
    tf32_gemm<<<ggrid, 256>>>(hidden, Wq, q, 1);
    tf32_gemm<<<ggrid, 256>>>(hidden, Wk, k, 1);
    tf32_gemm<<<ggrid, 256>>>(hidden, Wv, v, 1);

    rope_apply_kernel<<<(BH * SEQ * 64 + 255) / 256, 256>>>();

    flash_fwd<<<dim3(SEQ / 64, BH), 256, FLASH_SMEM_BYTES>>>(q, k, v, attn);

    tf32_gemm<<<ggrid, 256>>>(attn, Wo, out, 0);
}

// round 4
// speedup vs baseline: 3.0187x; 1.8217x over previous
#include <cuda_runtime.h>
#include <math.h>
#include <stdint.h>

#define BSZ    2
#define SEQ    2048
#define DMODEL 2048
#define NHEADS 16
#define HDIM   128
#define BH     (BSZ*NHEADS)
#define MROWS  (BSZ*SEQ)

// ---- scratch ----
__device__ float g_q[BH*SEQ*HDIM];
__device__ float g_k[BH*SEQ*HDIM];
__device__ float g_v[BH*SEQ*HDIM];
__device__ float g_attn[MROWS*DMODEL];
__device__ float g_cos[SEQ*64];
__device__ float g_sin[SEQ*64];

__device__ __forceinline__ float to_tf32(float x) {
    float y;
    asm("cvt.rna.tf32.f32 %0, %1;" : "=f"(y) : "f"(x));
    return y;
}
__device__ __forceinline__ void mma_tf32(float* c, const uint32_t* a, const uint32_t* b) {
    asm volatile(
        "mma.sync.aligned.m16n8k8.row.col.f32.tf32.tf32.f32 "
        "{%0,%1,%2,%3}, {%4,%5,%6,%7}, {%8,%9}, {%0,%1,%2,%3};"
        : "+f"(c[0]), "+f"(c[1]), "+f"(c[2]), "+f"(c[3])
        : "r"(a[0]), "r"(a[1]), "r"(a[2]), "r"(a[3]), "r"(b[0]), "r"(b[1]));
}
__device__ __forceinline__ float4 tf32x4(float4 v) {
    v.x = to_tf32(v.x); v.y = to_tf32(v.y); v.z = to_tf32(v.z); v.w = to_tf32(v.w);
    return v;
}

// =================== RoPE ===================
__global__ void rope_cache_kernel() {
    int idx = blockIdx.x * blockDim.x + threadIdx.x;
    if (idx >= SEQ * 64) return;
    int pos = idx >> 6, j = idx & 63;
    double e    = (double)(2 * j) / 128.0;
    double invf = pow(10000.0, -e);
    double ang  = (double)pos * invf;
    g_cos[idx] = (float)cos(ang);
    g_sin[idx] = (float)sin(ang);
}
__global__ void rope_apply_kernel() {
    int idx = blockIdx.x * blockDim.x + threadIdx.x;
    if (idx >= BH * SEQ * 64) return;
    int j = idx & 63, row = idx >> 6, s = row & (SEQ - 1);
    float c = g_cos[s * 64 + j], sn = g_sin[s * 64 + j];
    float* qp = g_q + (size_t)row * HDIM;
    float* kp = g_k + (size_t)row * HDIM;
    float q1 = qp[j], q2 = qp[j + 64];
    qp[j] = q1 * c - q2 * sn;  qp[j + 64] = q2 * c + q1 * sn;
    float k1 = kp[j], k2 = kp[j + 64];
    kp[j] = k1 * c - k2 * sn;  kp[j + 64] = k2 * c + k1 * sn;
}

// =================== TF32 GEMM (e-plane smem, double-buffered) ===================
// C[m,n] = sum_k A[m,k]*B[n,k]. 128x128 CTA tile, K stage 16, 8 warps (2m x 4n).
// A frag smem: slot = (mt*2+kb)*AT + e*AE + lane   (AE=36, AT=144)
// B frag smem: slot = (nt*2+kb)*BT + e*BE + lane   (BE=40, BT=80)
#define GEMM_K  DMODEL
#define KSTAGES (GEMM_K / 16)    // 128
#define AE 36
#define AT 144
#define BE 40
#define BT 80
#define A_STAGE (16*AT)          // 2304 words
#define B_STAGE (32*BT)          // 2560 words

__global__ __launch_bounds__(256, 2)
void tf32_gemm(const float* __restrict__ A, const float* __restrict__ B,
               float* __restrict__ C, int mode)
{
    __shared__ float As[2][A_STAGE];
    __shared__ float Bs[2][B_STAGE];

    const int tid  = threadIdx.x;
    const int wid  = tid >> 5;
    const int lane = tid & 31;
    const int bm = blockIdx.y * 128;
    const int bn = blockIdx.x * 128;
    const int wm = wid >> 2;          // 0..1
    const int wn = wid & 3;           // 0..3

    // load/scatter mapping: 2 float4 per operand per stage
    int aWord[2], bWord[2];
    const float4* Ap[2];
    const float4* Bp[2];
#pragma unroll
    for (int i = 0; i < 2; i++) {
        int f = i * 256 + tid;
        int row = f >> 2, c4 = f & 3;
        int kb = c4 >> 1, kh = c4 & 1;
        int g = row & 7, hi = (row >> 3) & 1;
        int mt = row >> 4, nt = row >> 3;
        aWord[i] = (mt * 2 + kb) * AT + (hi + 2 * kh) * AE + g * 4;
        bWord[i] = (nt * 2 + kb) * BT + kh * BE + g * 4;
        Ap[i] = (const float4*)(A + (size_t)(bm + row) * GEMM_K) + c4;
        Bp[i] = (const float4*)(B + (size_t)(bn + row) * GEMM_K) + c4;
    }

    float acc[4][4][4];
#pragma unroll
    for (int mt = 0; mt < 4; mt++)
#pragma unroll
        for (int nt = 0; nt < 4; nt++)
#pragma unroll
            for (int e = 0; e < 4; e++) acc[mt][nt][e] = 0.f;

    float4 pa[2], pb[2];
    // prologue: stage0 load+fill, stage1 load
#pragma unroll
    for (int i = 0; i < 2; i++) { pa[i] = Ap[i][0]; pb[i] = Bp[i][0]; }
#pragma unroll
    for (int i = 0; i < 2; i++) {
        *(float4*)&As[0][aWord[i]] = tf32x4(pa[i]);
        *(float4*)&Bs[0][bWord[i]] = tf32x4(pb[i]);
    }
#pragma unroll
    for (int i = 0; i < 2; i++) { pa[i] = Ap[i][4]; pb[i] = Bp[i][4]; }
    __syncthreads();

    const int aT0 = (wm * 4) * 2 * AT;
    const int bT0 = (wn * 4) * 2 * BT;

#pragma unroll 1
    for (int ks = 0; ks < KSTAGES; ks++) {
        const int buf = ks & 1;
        if (ks + 1 < KSTAGES) {
#pragma unroll
            for (int i = 0; i < 2; i++) {
                *(float4*)&As[buf ^ 1][aWord[i]] = tf32x4(pa[i]);
                *(float4*)&Bs[buf ^ 1][bWord[i]] = tf32x4(pb[i]);
            }
        }
        // MMA on buf
#pragma unroll
        for (int kb = 0; kb < 2; kb++) {
            uint32_t a[4][4], b[4][2];
#pragma unroll
            for (int mt = 0; mt < 4; mt++)
#pragma unroll
                for (int e = 0; e < 4; e++)
                    a[mt][e] = __float_as_uint(As[buf][aT0 + (mt * 2 + kb) * AT + e * AE + lane]);
#pragma unroll
            for (int nt = 0; nt < 4; nt++)
#pragma unroll
                for (int e = 0; e < 2; e++)
                    b[nt][e] = __float_as_uint(Bs[buf][bT0 + (nt * 2 + kb) * BT + e * BE + lane]);
#pragma unroll
            for (int mt = 0; mt < 4; mt++)
#pragma unroll
                for (int nt = 0; nt < 4; nt++)
                    mma_tf32(acc[mt][nt], a[mt], b[nt]);
        }
        if (ks + 2 < KSTAGES) {
#pragma unroll
            for (int i = 0; i < 2; i++) {
                pa[i] = Ap[i][(ks + 2) * 4];
                pb[i] = Bp[i][(ks + 2) * 4];
            }
        }
        __syncthreads();
    }

    // epilogue
    const int g = lane >> 2, tig = lane & 3;
#pragma unroll
    for (int mt = 0; mt < 4; mt++) {
#pragma unroll
        for (int nt = 0; nt < 4; nt++) {
            int row = bm + wm * 64 + mt * 16 + g;
            int col = bn + wn * 32 + nt * 8 + tig * 2;
            float* c0;
            size_t rstride;
            if (mode == 0) {
                c0 = C + (size_t)row * DMODEL + col;
                rstride = DMODEL;
            } else {
                int b = row >> 11, s = row & (SEQ - 1);
                int h = col >> 7, hd = col & 127;
                c0 = C + (((size_t)(b * NHEADS + h)) * SEQ + s) * HDIM + hd;
                rstride = HDIM;
            }
            *(float2*)c0 = make_float2(acc[mt][nt][0], acc[mt][nt][1]);
            *(float2*)(c0 + 8 * rstride) = make_float2(acc[mt][nt][2], acc[mt][nt][3]);
        }
    }
}

// =================== Flash attention (causal, tf32 mma) ===================
// 64 q-rows/CTA, 64-kv tiles, 256 threads (8 warps: wm(2) x wn(4)).
// Qf: vector a-frag layout, tile stride 132: slot = (mt*16+kt)*132 + lane*4 + e
// Kf: e-plane b-frag:  slot = (nt*16+kt)*72 + e*36 + lane
// Vf: e-plane b-frag:  slot = nt*580 + kt*72 + e*36 + lane
// Ps: 64 x 68 scores tile.
#define QTS 132
#define KE  36
#define KTS 72
#define VTS 580
#define OFF_KF 8448
#define OFF_VF 17664
#define OFF_PS 26944
#define OFF_RM 31296
#define FLASH_SMEM_BYTES ((OFF_RM + 3*64) * 4)   // 125952 B

__global__ __launch_bounds__(256)
void flash_fwd(const float* __restrict__ Qg, const float* __restrict__ Kg,
               const float* __restrict__ Vg, float* __restrict__ Og)
{
    extern __shared__ float smf[];
    float* Qf = smf;
    float* Kf = smf + OFF_KF;
    float* Vf = smf + OFF_VF;
    float* Ps = smf + OFF_PS;
    float* rm = smf + OFF_RM;
    float* rl = rm + 64;
    float* ra = rl + 64;

    const int tid  = threadIdx.x;
    const int wid  = tid >> 5;
    const int lane = tid & 31;
    const int g4 = lane >> 2, tig = lane & 3;
    const int wm = wid >> 2;          // 0..1 (32 rows)
    const int wn = wid & 3;           // 0..3
    const int bx = blockIdx.x;
    const int bh = blockIdx.y;
    const int m0 = bx * 64;
    const size_t base = (size_t)bh * SEQ * HDIM;
    const float scale = 0.08838834764831845f;

    // ---- load Q -> Qf (a-frag, tf32) ----
#pragma unroll
    for (int i = 0; i < 8; i++) {
        int row = i * 8 + wid;                     // 0..63
        float4 v = *(const float4*)(Qg + base + (size_t)(m0 + row) * HDIM + lane * 4);
        v = tf32x4(v);
        int mt = row >> 4, g = row & 7, hi = (row >> 3) & 1;
        int kt = lane >> 1, kh = lane & 1;
        int w = (mt * 16 + kt) * QTS + 16 * g + (hi + 2 * kh);
        Qf[w + 0] = v.x; Qf[w + 4] = v.y; Qf[w + 8] = v.z; Qf[w + 12] = v.w;
    }
    if (tid < 64) { rm[tid] = -1e30f; rl[tid] = 0.f; }

    float o[2][4][4];
#pragma unroll
    for (int mt = 0; mt < 2; mt++)
#pragma unroll
        for (int nt = 0; nt < 4; nt++)
#pragma unroll
            for (int e = 0; e < 4; e++) o[mt][nt][e] = 0.f;

    const int ntiles = bx + 1;
    for (int t = 0; t < ntiles; t++) {
        const int n0 = t * 64;
        __syncthreads();  // prev PV done with Vf/Ps; Qf/stats visible (1st iter)

        // ---- load K,V tiles ----
#pragma unroll
        for (int i = 0; i < 8; i++) {
            int row = i * 8 + wid;
            const float* src = (const float*)(Kg + base + (size_t)(n0 + row) * HDIM) + lane * 4;
            float4 kv = tf32x4(*(const float4*)src);
            {   // K: n=row, k=4*lane+j
                int g = row & 7, nt = row >> 3;
                int kt = lane >> 1, kh = lane & 1;
                *(float4*)&Kf[(nt * 16 + kt) * KTS + kh * KE + g * 4] = kv;
            }
            float4 vv = tf32x4(*(const float4*)(Vg + base + (size_t)(n0 + row) * HDIM + lane * 4));
            {   // V: k=row, n=4*lane+j
                int ktv = row >> 3, ev = (row >> 2) & 1, gk = row & 3;
                float vj[4] = {vv.x, vv.y, vv.z, vv.w};
#pragma unroll
                for (int j = 0; j < 4; j++) {
                    int n = 4 * lane + j;
                    Vf[(n >> 3) * VTS + ktv * KTS + ev * KE + ((n & 7) << 2) + gk] = vj[j];
                }
            }
        }
        __syncthreads();

        // ---- S = Q K^T : warp tile 32m x 16n ----
        float s[2][2][4];
#pragma unroll
        for (int mt = 0; mt < 2; mt++)
#pragma unroll
            for (int nt = 0; nt < 2; nt++)
#pragma unroll
                for (int e = 0; e < 4; e++) s[mt][nt][e] = 0.f;

#pragma unroll
        for (int kt = 0; kt < 16; kt++) {
            uint32_t a[2][4], b[2][2];
#pragma unroll
            for (int mt = 0; mt < 2; mt++)
                *(uint4*)a[mt] = *(const uint4*)&Qf[((wm * 2 + mt) * 16 + kt) * QTS + lane * 4];
#pragma unroll
            for (int nt = 0; nt < 2; nt++)
#pragma unroll
                for (int e = 0; e < 2; e++)
                    b[nt][e] = __float_as_uint(Kf[((wn * 2 + nt) * 16 + kt) * KTS + e * KE + lane]);
#pragma unroll
            for (int mt = 0; mt < 2; mt++)
#pragma unroll
                for (int nt = 0; nt < 2; nt++)
                    mma_tf32(s[mt][nt], a[mt], b[nt]);
        }

        // ---- write scores (scale + causal mask) ----
        const bool diag = (t == bx);
#pragma unroll
        for (int mt = 0; mt < 2; mt++) {
#pragma unroll
            for (int nt = 0; nt < 2; nt++) {
                int r0 = wm * 32 + mt * 16 + g4;
                int c0 = wn * 16 + nt * 8 + 2 * tig;
#pragma unroll
                for (int h = 0; h < 2; h++) {   // h=0: rows r0, h=1: rows r0+8
                    int rr = r0 + h * 8;
                    float v0 = s[mt][nt][2 * h + 0] * scale;
                    float v1 = s[mt][nt][2 * h + 1] * scale;
                    if (diag) {
                        int grow = m0 + rr;
                        if (n0 + c0     > grow) v0 = -1e30f;
                        if (n0 + c0 + 1 > grow) v1 = -1e30f;
                    }
                    *(float2*)&Ps[rr * 68 + c0] = make_float2(v0, v1);
                }
            }
        }
        __syncthreads();

        // ---- online softmax: 4 threads per row ----
        {
            int row = tid >> 2, q = tid & 3;
            float* pr = Ps + row * 68 + q * 16;
            float mo = rm[row];
            float mx = mo;
#pragma unroll
            for (int c = 0; c < 16; c++) mx = fmaxf(mx, pr[c]);
            mx = fmaxf(mx, __shfl_xor_sync(0xFFFFFFFFu, mx, 1));
            mx = fmaxf(mx, __shfl_xor_sync(0xFFFFFFFFu, mx, 2));
            float l = 0.f;
#pragma unroll
            for (int c = 0; c < 16; c++) {
                float p = __expf(pr[c] - mx);
                l += p;
                pr[c] = to_tf32(p);
            }
            l += __shfl_xor_sync(0xFFFFFFFFu, l, 1);
            l += __shfl_xor_sync(0xFFFFFFFFu, l, 2);
            if (q == 0) {
                float alpha = __expf(mo - mx);
                rl[row] = rl[row] * alpha + l;
                rm[row] = mx;
                ra[row] = alpha;
            }
        }
        __syncthreads();

        // ---- PV: O += P V, warp tile 32m x 32n ----
        {
            int rb0 = wm * 32 + g4;
            float al[2][2];
#pragma unroll
            for (int mt = 0; mt < 2; mt++) {
                al[mt][0] = ra[rb0 + mt * 16];
                al[mt][1] = ra[rb0 + mt * 16 + 8];
            }
#pragma unroll
            for (int mt = 0; mt < 2; mt++)
#pragma unroll
                for (int nt = 0; nt < 4; nt++) {
                    o[mt][nt][0] *= al[mt][0]; o[mt][nt][1] *= al[mt][0];
                    o[mt][nt][2] *= al[mt][1]; o[mt][nt][3] *= al[mt][1];
                }
#pragma unroll
            for (int kt = 0; kt < 8; kt++) {
                uint32_t a[2][4], b[4][2];
#pragma unroll
                for (int mt = 0; mt < 2; mt++) {
                    int rb = wm * 32 + mt * 16;
                    a[mt][0] = __float_as_uint(Ps[(rb + g4) * 68 + kt * 8 + tig]);
                    a[mt][1] = __float_as_uint(Ps[(rb + 8 + g4) * 68 + kt * 8 + tig]);
                    a[mt][2] = __float_as_uint(Ps[(rb + g4) * 68 + kt * 8 + tig + 4]);
                    a[mt][3] = __float_as_uint(Ps[(rb + 8 + g4) * 68 + kt * 8 + tig + 4]);
                }
#pragma unroll
                for (int nt = 0; nt < 4; nt++)
#pragma unroll
                    for (int e = 0; e < 2; e++)
                        b[nt][e] = __float_as_uint(Vf[(wn * 4 + nt) * VTS + kt * KTS + e * KE + lane]);
#pragma unroll
                for (int mt = 0; mt < 2; mt++)
#pragma unroll
                    for (int nt = 0; nt < 4; nt++)
                        mma_tf32(o[mt][nt], a[mt], b[nt]);
            }
        }
    }

    // ---- epilogue ----
    const int b = bh >> 4, h = bh & 15;
#pragma unroll
    for (int mt = 0; mt < 2; mt++) {
        int rloc0 = wm * 32 + mt * 16 + g4;
#pragma unroll
        for (int hh = 0; hh < 2; hh++) {
            int rloc = rloc0 + hh * 8;
            float inv = 1.f / rl[rloc];
            int srow = m0 + rloc;
            float* op = Og + ((size_t)(b * SEQ + srow)) * DMODEL + h * HDIM;
#pragma unroll
            for (int nt = 0; nt < 4; nt++) {
                int col = wn * 32 + nt * 8 + 2 * tig;
                *(float2*)(op + col) = make_float2(o[mt][nt][2 * hh] * inv,
                                                   o[mt][nt][2 * hh + 1] * inv);
            }
        }
    }
}

// =================== launch ===================
extern "C" void kernel_launch(void* const* d_in, const int* in_sizes, int n_in,
                              void* d_out, int out_size)
{
    (void)in_sizes; (void)n_in; (void)out_size;
    const float* hidden = (const float*)d_in[0];
    const float* Wq = (const float*)d_in[3];
    const float* Wk = (const float*)d_in[4];
    const float* Wv = (const float*)d_in[5];
    const float* Wo = (const float*)d_in[6];
    float* out = (float*)d_out;

    float *q, *k, *v, *attn;
    cudaGetSymbolAddress((void**)&q,    g_q);
    cudaGetSymbolAddress((void**)&k,    g_k);
    cudaGetSymbolAddress((void**)&v,    g_v);
    cudaGetSymbolAddress((void**)&attn, g_attn);

    cudaFuncSetAttribute(flash_fwd, cudaFuncAttributeMaxDynamicSharedMemorySize,
                         FLASH_SMEM_BYTES);

    rope_cache_kernel<<<(SEQ * 64 + 255) / 256, 256>>>();

    dim3 ggrid(DMODEL / 128, MROWS / 128);   // (16, 32)
    tf32_gemm<<<ggrid, 256>>>(hidden, Wq, q, 1);
    tf32_gemm<<<ggrid, 256>>>(hidden, Wk, k, 1);
    tf32_gemm<<<ggrid, 256>>>(hidden, Wv, v, 1);

    rope_apply_kernel<<<(BH * SEQ * 64 + 255) / 256, 256>>>();

    flash_fwd<<<dim3(SEQ / 64, BH), 256, FLASH_SMEM_BYTES>>>(q, k, v, attn);

    tf32_gemm<<<ggrid, 256>>>(attn, Wo, out, 0);
}